// round 1
// baseline (speedup 1.0000x reference)
#include <cuda_runtime.h>
#include <math.h>

#define BB 8
#define LL 1024
#define DD 512
#define HH 8
#define DKK 64

// Scratch (allowed: __device__ globals, no runtime allocation)
__device__ float g_Q[BB*HH*LL*DKK];   // (B,H,L,DK)
__device__ float g_K[BB*HH*LL*DKK];
__device__ float g_V[BB*HH*LL*DKK];
__device__ float g_X[BB*LL*DD];       // attention output, (B,L,D)

// ---------------------------------------------------------------------------
// GEMM: C[m,n] = sum_k A[m,k] * W[n,k] + bias[n]
// M = 8192 (B*L), N = 512 (D), K = 512 (D). 64x64 tile, K-tile 16,
// 256 threads, 4x4 register tile per thread.
// headmode=1: scatter into (B,H,L,DK) layout. headmode=0: row-major (M,N).
// ---------------------------------------------------------------------------
__global__ __launch_bounds__(256) void gemm_kernel(
    const float* __restrict__ A, const float* __restrict__ W,
    const float* __restrict__ bias, float* __restrict__ C, int headmode)
{
    __shared__ float As[64][17];
    __shared__ float Bs[16][65];

    const int tid = threadIdx.x;
    const int tx = tid & 15, ty = tid >> 4;
    const int m0 = blockIdx.y << 6, n0 = blockIdx.x << 6;

    float acc[4][4] = {};

    const int lr = tid >> 2;          // 0..63
    const int lc = (tid & 3) << 2;    // 0,4,8,12
    const float* Ap = A + (size_t)(m0 + lr) * DD + lc;
    const float* Wp = W + (size_t)(n0 + lr) * DD + lc;

    for (int k0 = 0; k0 < DD; k0 += 16) {
        float4 a4 = *(const float4*)(Ap + k0);
        float4 w4 = *(const float4*)(Wp + k0);
        As[lr][lc]   = a4.x; As[lr][lc+1] = a4.y;
        As[lr][lc+2] = a4.z; As[lr][lc+3] = a4.w;
        Bs[lc][lr]   = w4.x; Bs[lc+1][lr] = w4.y;
        Bs[lc+2][lr] = w4.z; Bs[lc+3][lr] = w4.w;
        __syncthreads();
        #pragma unroll
        for (int kk = 0; kk < 16; kk++) {
            float a[4], b[4];
            #pragma unroll
            for (int i = 0; i < 4; i++) a[i] = As[ty*4+i][kk];
            #pragma unroll
            for (int j = 0; j < 4; j++) b[j] = Bs[kk][tx*4+j];
            #pragma unroll
            for (int i = 0; i < 4; i++)
                #pragma unroll
                for (int j = 0; j < 4; j++)
                    acc[i][j] = fmaf(a[i], b[j], acc[i][j]);
        }
        __syncthreads();
    }

    float bv[4];
    #pragma unroll
    for (int j = 0; j < 4; j++) bv[j] = bias[n0 + tx*4 + j];

    if (headmode) {
        #pragma unroll
        for (int i = 0; i < 4; i++) {
            int m = m0 + ty*4 + i;
            int b_ = m >> 10, l = m & 1023;
            #pragma unroll
            for (int j = 0; j < 4; j++) {
                int n = n0 + tx*4 + j;
                int h = n >> 6, dk = n & 63;
                C[(((size_t)b_*HH + h)*LL + l)*DKK + dk] = acc[i][j] + bv[j];
            }
        }
    } else {
        #pragma unroll
        for (int i = 0; i < 4; i++) {
            int m = m0 + ty*4 + i;
            #pragma unroll
            for (int j = 0; j < 4; j++)
                C[(size_t)m*DD + n0 + tx*4 + j] = acc[i][j] + bv[j];
        }
    }
}

// ---------------------------------------------------------------------------
// Flash-style attention: one block per (bh, 64 q-rows). Never materializes
// the full score matrix. Online softmax with per-head distance bias + mask.
// Dynamic smem: Q,K,V,P tiles of 64x65 floats each (66,560 B).
// ---------------------------------------------------------------------------
#define SMEM_ATTN (4 * 64 * 65 * (int)sizeof(float))

__global__ __launch_bounds__(256) void attn_kernel(
    const float* __restrict__ dist, const unsigned char* __restrict__ mask,
    const float* __restrict__ logwb)
{
    extern __shared__ float sm[];
    float* Qs = sm;
    float* Ks = sm + 64*65;
    float* Vs = sm + 2*64*65;
    float* Ps = sm + 3*64*65;

    const int bh = blockIdx.y;
    const int b  = bh >> 3, h = bh & 7;
    const int q0 = blockIdx.x << 6;
    const int tid = threadIdx.x;
    const int tx = tid & 15, ty = tid >> 4;
    const int r0 = ty << 2, c0 = tx << 2;

    const float wb = __expf(logwb[h]);

    // Load Q tile
    const float* Qg = g_Q + ((size_t)bh * LL + q0) * DKK;
    for (int i = tid; i < 64*DKK/4; i += 256) {
        int r = i >> 4, c = (i & 15) << 2;
        float4 v = *(const float4*)(Qg + r*DKK + c);
        Qs[r*65+c] = v.x; Qs[r*65+c+1] = v.y; Qs[r*65+c+2] = v.z; Qs[r*65+c+3] = v.w;
    }

    float m_i[4], l_i[4], acc[4][4];
    #pragma unroll
    for (int i = 0; i < 4; i++) {
        m_i[i] = -1e30f; l_i[i] = 0.f;
        #pragma unroll
        for (int j = 0; j < 4; j++) acc[i][j] = 0.f;
    }

    const float* Kg = g_K + (size_t)bh * LL * DKK;
    const float* Vg = g_V + (size_t)bh * LL * DKK;
    const float* db = dist + (size_t)b * LL * LL;
    const unsigned char* mb = mask + (size_t)b * LL * LL;

    for (int kt = 0; kt < LL; kt += 64) {
        __syncthreads();   // protect Ks/Vs/Ps from previous iteration readers
        for (int i = tid; i < 64*DKK/4; i += 256) {
            int r = i >> 4, c = (i & 15) << 2;
            float4 kv = *(const float4*)(Kg + (size_t)(kt + r)*DKK + c);
            Ks[r*65+c] = kv.x; Ks[r*65+c+1] = kv.y; Ks[r*65+c+2] = kv.z; Ks[r*65+c+3] = kv.w;
            float4 vv = *(const float4*)(Vg + (size_t)(kt + r)*DKK + c);
            Vs[r*65+c] = vv.x; Vs[r*65+c+1] = vv.y; Vs[r*65+c+2] = vv.z; Vs[r*65+c+3] = vv.w;
        }
        __syncthreads();

        // S = Q * K^T (4x4 per thread)
        float s[4][4] = {};
        #pragma unroll 8
        for (int kk = 0; kk < DKK; kk++) {
            float a[4], k2[4];
            #pragma unroll
            for (int i = 0; i < 4; i++) a[i] = Qs[(r0+i)*65 + kk];
            #pragma unroll
            for (int j = 0; j < 4; j++) k2[j] = Ks[(c0+j)*65 + kk];
            #pragma unroll
            for (int i = 0; i < 4; i++)
                #pragma unroll
                for (int j = 0; j < 4; j++)
                    s[i][j] = fmaf(a[i], k2[j], s[i][j]);
        }

        // scale, distance bias, mask
        #pragma unroll
        for (int i = 0; i < 4; i++) {
            int qr = q0 + r0 + i;
            float4 d4 = *(const float4*)(db + (size_t)qr*LL + kt + c0);
            unsigned mk = *(const unsigned*)(mb + (size_t)qr*LL + kt + c0);
            float dv[4] = {d4.x, d4.y, d4.z, d4.w};
            #pragma unroll
            for (int j = 0; j < 4; j++) {
                float sv = s[i][j]*0.125f - dv[j]*wb;
                if ((mk >> (8*j)) & 0xffu) sv = -1e9f;
                s[i][j] = sv;
            }
        }

        // online softmax (row reductions across the 16 tx lanes via shfl)
        #pragma unroll
        for (int i = 0; i < 4; i++) {
            float rmax = fmaxf(fmaxf(s[i][0], s[i][1]), fmaxf(s[i][2], s[i][3]));
            #pragma unroll
            for (int o = 8; o; o >>= 1)
                rmax = fmaxf(rmax, __shfl_xor_sync(0xffffffffu, rmax, o));
            float mnew  = fmaxf(m_i[i], rmax);
            float alpha = __expf(m_i[i] - mnew);
            float rsum = 0.f;
            #pragma unroll
            for (int j = 0; j < 4; j++) { s[i][j] = __expf(s[i][j] - mnew); rsum += s[i][j]; }
            #pragma unroll
            for (int o = 8; o; o >>= 1)
                rsum += __shfl_xor_sync(0xffffffffu, rsum, o);
            l_i[i] = l_i[i]*alpha + rsum;
            m_i[i] = mnew;
            #pragma unroll
            for (int j = 0; j < 4; j++) {
                acc[i][j] *= alpha;
                Ps[(r0+i)*65 + c0+j] = s[i][j];
            }
        }
        __syncthreads();

        // O += P * V
        #pragma unroll 8
        for (int kk = 0; kk < 64; kk++) {
            float p[4], v2[4];
            #pragma unroll
            for (int i = 0; i < 4; i++) p[i] = Ps[(r0+i)*65 + kk];
            #pragma unroll
            for (int j = 0; j < 4; j++) v2[j] = Vs[kk*65 + c0+j];
            #pragma unroll
            for (int i = 0; i < 4; i++)
                #pragma unroll
                for (int j = 0; j < 4; j++)
                    acc[i][j] = fmaf(p[i], v2[j], acc[i][j]);
        }
    }

    // normalize + write to (B,L,D)
    #pragma unroll
    for (int i = 0; i < 4; i++) {
        float inv = 1.0f / l_i[i];
        int qr = q0 + r0 + i;
        float* xr = g_X + ((size_t)b*LL + qr)*DD + h*DKK;
        #pragma unroll
        for (int j = 0; j < 4; j++) xr[c0+j] = acc[i][j] * inv;
    }
}

// ---------------------------------------------------------------------------
extern "C" void kernel_launch(void* const* d_in, const int* in_sizes, int n_in,
                              void* d_out, int out_size)
{
    const float* query = (const float*)d_in[0];
    const float* key   = (const float*)d_in[1];
    const float* value = (const float*)d_in[2];
    const float* dist  = (const float*)d_in[3];
    const unsigned char* mask = (const unsigned char*)d_in[4];
    const float* Wq = (const float*)d_in[5];
    const float* bq = (const float*)d_in[6];
    const float* Wk = (const float*)d_in[7];
    const float* bk = (const float*)d_in[8];
    const float* Wv = (const float*)d_in[9];
    const float* bv = (const float*)d_in[10];
    const float* Wo = (const float*)d_in[11];
    const float* bo = (const float*)d_in[12];
    const float* logwb = (const float*)d_in[13];

    void *pQ, *pK, *pV, *pX;
    cudaGetSymbolAddress(&pQ, g_Q);
    cudaGetSymbolAddress(&pK, g_K);
    cudaGetSymbolAddress(&pV, g_V);
    cudaGetSymbolAddress(&pX, g_X);

    cudaFuncSetAttribute(attn_kernel,
                         cudaFuncAttributeMaxDynamicSharedMemorySize, SMEM_ATTN);

    dim3 gg(DD/64, BB*LL/64);   // (8, 128)
    gemm_kernel<<<gg, 256>>>(query, Wq, bq, (float*)pQ, 1);
    gemm_kernel<<<gg, 256>>>(key,   Wk, bk, (float*)pK, 1);
    gemm_kernel<<<gg, 256>>>(value, Wv, bv, (float*)pV, 1);

    attn_kernel<<<dim3(LL/64, BB*HH), 256, SMEM_ATTN>>>(dist, mask, logwb);

    gemm_kernel<<<gg, 256>>>((const float*)pX, Wo, bo, (float*)d_out, 0);
}

// round 3
// speedup vs baseline: 1.4389x; 1.4389x over previous
#include <cuda_runtime.h>
#include <math.h>

#define BB 8
#define LL 1024
#define DD 512
#define HH 8
#define DKK 64

// Scratch (__device__ globals; no runtime allocation)
__device__ float g_Q[BB*HH*LL*DKK];   // (B,H,L,DK) fp32
__device__ float g_K[BB*HH*LL*DKK];
__device__ float g_V[BB*HH*LL*DKK];
__device__ float g_X[BB*LL*DD];       // attention output (B,L,D) fp32

// m16n8k8 tf32 MMA. A row-major (16x8), B col-major (8x8), C fp32.
__device__ __forceinline__ void mma8(float* c, const unsigned* a, unsigned b0, unsigned b1) {
    asm volatile(
        "mma.sync.aligned.m16n8k8.row.col.f32.tf32.tf32.f32 "
        "{%0,%1,%2,%3}, {%4,%5,%6,%7}, {%8,%9}, {%0,%1,%2,%3};\n"
        : "+f"(c[0]), "+f"(c[1]), "+f"(c[2]), "+f"(c[3])
        : "r"(a[0]), "r"(a[1]), "r"(a[2]), "r"(a[3]), "r"(b0), "r"(b1));
}

// round-to-nearest tf32 (result has low 13 bits zero; reinterpretable as float)
__device__ __forceinline__ unsigned f2tf(float x) {
    unsigned r;
    asm("cvt.rna.tf32.f32 %0, %1;" : "=r"(r) : "f"(x));
    return r;
}
__device__ __forceinline__ void split_tf(float x, unsigned& hi, unsigned& lo) {
    hi = f2tf(x);
    lo = f2tf(x - __uint_as_float(hi));
}

// ---------------------------------------------------------------------------
// 3xTF32 tensor-core GEMM: C[m,n] = sum_k A[m,k]*W[n,k] + bias[n]
// M=8192, N=512, K=512. Block tile 128x64, BK=32, 256 threads (8 warps, 4x2),
// warp tile 32x32 (2 m-tiles x 4 n-tiles of m16n8k8), each MMA done 3x
// (hi*hi + lo*hi + hi*lo) for ~fp32 accuracy.
// ---------------------------------------------------------------------------
#define GST 36   // smem row stride (36 % 32 == 4 -> conflict-free frag loads)

__global__ __launch_bounds__(256) void gemm_tf32(
    const float* __restrict__ A, const float* __restrict__ W,
    const float* __restrict__ bias, float* __restrict__ C, int headmode)
{
    __shared__ float As[128][GST];
    __shared__ float Bs[64][GST];

    const int tid  = threadIdx.x;
    const int lane = tid & 31;
    const int warp = tid >> 5;
    const int g = lane >> 2, t = lane & 3;
    const int wm = warp & 3, wn = warp >> 2;     // 4 (m) x 2 (n)
    const int m0 = blockIdx.y << 7, n0 = blockIdx.x << 6;

    float c[2][4][4];
    #pragma unroll
    for (int mt = 0; mt < 2; mt++)
        #pragma unroll
        for (int nt = 0; nt < 4; nt++)
            #pragma unroll
            for (int k = 0; k < 4; k++) c[mt][nt][k] = 0.f;

    const float* Abase = A + (size_t)m0 * DD;
    const float* Wbase = W + (size_t)n0 * DD;

    float4 ra[4], rb[2];
    #pragma unroll
    for (int i = 0; i < 4; i++) {
        int idx = tid + (i << 8);
        ra[i] = *(const float4*)(Abase + (size_t)(idx >> 3) * DD + ((idx & 7) << 2));
    }
    #pragma unroll
    for (int i = 0; i < 2; i++) {
        int idx = tid + (i << 8);
        rb[i] = *(const float4*)(Wbase + (size_t)(idx >> 3) * DD + ((idx & 7) << 2));
    }

    for (int k0 = 0; k0 < DD; k0 += 32) {
        __syncthreads();
        #pragma unroll
        for (int i = 0; i < 4; i++) {
            int idx = tid + (i << 8);
            *(float4*)&As[idx >> 3][(idx & 7) << 2] = ra[i];
        }
        #pragma unroll
        for (int i = 0; i < 2; i++) {
            int idx = tid + (i << 8);
            *(float4*)&Bs[idx >> 3][(idx & 7) << 2] = rb[i];
        }
        __syncthreads();

        if (k0 + 32 < DD) {
            #pragma unroll
            for (int i = 0; i < 4; i++) {
                int idx = tid + (i << 8);
                ra[i] = *(const float4*)(Abase + (size_t)(idx >> 3) * DD + k0 + 32 + ((idx & 7) << 2));
            }
            #pragma unroll
            for (int i = 0; i < 2; i++) {
                int idx = tid + (i << 8);
                rb[i] = *(const float4*)(Wbase + (size_t)(idx >> 3) * DD + k0 + 32 + ((idx & 7) << 2));
            }
        }

        #pragma unroll
        for (int kt = 0; kt < 4; kt++) {
            unsigned ah[2][4], al[2][4], bh[4][2], bl[4][2];
            #pragma unroll
            for (int mt = 0; mt < 2; mt++) {
                int r = wm * 32 + mt * 16 + g;
                split_tf(As[r    ][kt*8 + t    ], ah[mt][0], al[mt][0]);
                split_tf(As[r + 8][kt*8 + t    ], ah[mt][1], al[mt][1]);
                split_tf(As[r    ][kt*8 + t + 4], ah[mt][2], al[mt][2]);
                split_tf(As[r + 8][kt*8 + t + 4], ah[mt][3], al[mt][3]);
            }
            #pragma unroll
            for (int nt = 0; nt < 4; nt++) {
                int r = wn * 32 + nt * 8 + g;
                split_tf(Bs[r][kt*8 + t    ], bh[nt][0], bl[nt][0]);
                split_tf(Bs[r][kt*8 + t + 4], bh[nt][1], bl[nt][1]);
            }
            #pragma unroll
            for (int mt = 0; mt < 2; mt++)
                #pragma unroll
                for (int nt = 0; nt < 4; nt++) {
                    mma8(c[mt][nt], al[mt], bh[nt][0], bh[nt][1]);
                    mma8(c[mt][nt], ah[mt], bl[nt][0], bl[nt][1]);
                    mma8(c[mt][nt], ah[mt], bh[nt][0], bh[nt][1]);
                }
        }
    }

    // epilogue: bias + store
    #pragma unroll
    for (int nt = 0; nt < 4; nt++) {
        int n = n0 + wn * 32 + nt * 8 + 2 * t;
        float b0 = bias[n], b1 = bias[n + 1];
        #pragma unroll
        for (int mt = 0; mt < 2; mt++) {
            int m = m0 + wm * 32 + mt * 16 + g;
            if (headmode) {
                int b_ = m >> 10, l = m & 1023;
                int h = n >> 6, dk = n & 63;
                float* p0 = C + (((size_t)b_ * HH + h) * LL + l) * DKK + dk;
                float* p1 = C + (((size_t)b_ * HH + h) * LL + (l + 8)) * DKK + dk;
                *(float2*)p0 = make_float2(c[mt][nt][0] + b0, c[mt][nt][1] + b1);
                *(float2*)p1 = make_float2(c[mt][nt][2] + b0, c[mt][nt][3] + b1);
            } else {
                float* p0 = C + (size_t)m * DD + n;
                float* p1 = C + (size_t)(m + 8) * DD + n;
                *(float2*)p0 = make_float2(c[mt][nt][0] + b0, c[mt][nt][1] + b1);
                *(float2*)p1 = make_float2(c[mt][nt][2] + b0, c[mt][nt][3] + b1);
            }
        }
    }
}

// ---------------------------------------------------------------------------
// Flash attention, tf32 MMA with precision splits.
// Block = (bh, 64 q-rows), 128 threads (4 warps, 16 q-rows each).
// QK^T: 3xTF32 (Q hi/lo register-resident; K hi/lo smem tiles).
// P@V : 2xTF32 (P rounded to tf32-rna once; V hi/lo smem tiles).
// smem: Ksh,Ksl,Vsh,Vsl,Ps = 5 x 64 x 68 floats = 87,040 B dynamic.
// ---------------------------------------------------------------------------
#define AST 68
#define SMEM_ATTN (5 * 64 * AST * (int)sizeof(float))

__global__ __launch_bounds__(128) void attn_tf32(
    const float* __restrict__ dist, const unsigned char* __restrict__ mask,
    const float* __restrict__ logwb)
{
    extern __shared__ float sm[];
    float* Ksh = sm;
    float* Ksl = sm + 64 * AST;
    float* Vsh = sm + 2 * 64 * AST;
    float* Vsl = sm + 3 * 64 * AST;
    float* Ps  = sm + 4 * 64 * AST;

    const int tid  = threadIdx.x;
    const int lane = tid & 31;
    const int warp = tid >> 5;
    const int g = lane >> 2, t = lane & 3;

    const int bh = blockIdx.y;
    const int b  = bh >> 3, h = bh & 7;
    const int q0 = blockIdx.x << 6;

    const float wb = __expf(logwb[h]);

    // Stage Q (scaled by 0.125) through Ksh, then split into hi/lo A-frags.
    const float* Qg = g_Q + ((size_t)bh * LL + q0) * DKK;
    for (int i = tid; i < 1024; i += 128) {          // 64 rows x 16 float4
        int r = i >> 4, c4 = (i & 15) << 2;
        float4 v = *(const float4*)(Qg + (size_t)r * DKK + c4);
        v.x *= 0.125f; v.y *= 0.125f; v.z *= 0.125f; v.w *= 0.125f;
        *(float4*)&Ksh[r * AST + c4] = v;
    }
    __syncthreads();

    unsigned qh[8][4], ql[8][4];
    {
        int r = warp * 16 + g;
        #pragma unroll
        for (int kt = 0; kt < 8; kt++) {
            split_tf(Ksh[ r      * AST + kt*8 + t    ], qh[kt][0], ql[kt][0]);
            split_tf(Ksh[(r + 8) * AST + kt*8 + t    ], qh[kt][1], ql[kt][1]);
            split_tf(Ksh[ r      * AST + kt*8 + t + 4], qh[kt][2], ql[kt][2]);
            split_tf(Ksh[(r + 8) * AST + kt*8 + t + 4], qh[kt][3], ql[kt][3]);
        }
    }

    float o[8][4];
    #pragma unroll
    for (int nt = 0; nt < 8; nt++)
        #pragma unroll
        for (int k = 0; k < 4; k++) o[nt][k] = 0.f;
    float mrow[2] = {-1e30f, -1e30f};
    float lrow[2] = {0.f, 0.f};

    const float* Kg = g_K + (size_t)bh * LL * DKK;
    const float* Vg = g_V + (size_t)bh * LL * DKK;
    const float* db = dist + (size_t)b * LL * LL;
    const unsigned char* mb = mask + (size_t)b * LL * LL;

    const int qr0 = q0 + warp * 16 + g;   // global q row for c0/c1; +8 for c2/c3
    const int pr0 = warp * 16 + g;        // local P row

    for (int k0 = 0; k0 < LL; k0 += 64) {
        __syncthreads();   // all warps done with previous tiles
        for (int i = tid; i < 1024; i += 128) {
            int r = i >> 4, c4 = (i & 15) << 2;
            float4 kv = *(const float4*)(Kg + (size_t)(k0 + r) * DKK + c4);
            float4 vv = *(const float4*)(Vg + (size_t)(k0 + r) * DKK + c4);
            float4 khi, klo, vhi, vlo;
            unsigned uh, ul;
            split_tf(kv.x, uh, ul); khi.x = __uint_as_float(uh); klo.x = __uint_as_float(ul);
            split_tf(kv.y, uh, ul); khi.y = __uint_as_float(uh); klo.y = __uint_as_float(ul);
            split_tf(kv.z, uh, ul); khi.z = __uint_as_float(uh); klo.z = __uint_as_float(ul);
            split_tf(kv.w, uh, ul); khi.w = __uint_as_float(uh); klo.w = __uint_as_float(ul);
            split_tf(vv.x, uh, ul); vhi.x = __uint_as_float(uh); vlo.x = __uint_as_float(ul);
            split_tf(vv.y, uh, ul); vhi.y = __uint_as_float(uh); vlo.y = __uint_as_float(ul);
            split_tf(vv.z, uh, ul); vhi.z = __uint_as_float(uh); vlo.z = __uint_as_float(ul);
            split_tf(vv.w, uh, ul); vhi.w = __uint_as_float(uh); vlo.w = __uint_as_float(ul);
            *(float4*)&Ksh[r * AST + c4] = khi;
            *(float4*)&Ksl[r * AST + c4] = klo;
            *(float4*)&Vsh[r * AST + c4] = vhi;
            *(float4*)&Vsl[r * AST + c4] = vlo;
        }
        __syncthreads();

        // S = Q @ K^T with 3xTF32
        float s[8][4];
        #pragma unroll
        for (int nt = 0; nt < 8; nt++)
            #pragma unroll
            for (int k = 0; k < 4; k++) s[nt][k] = 0.f;

        #pragma unroll
        for (int kt = 0; kt < 8; kt++) {
            #pragma unroll
            for (int nt = 0; nt < 8; nt++) {
                int br = (nt*8 + g) * AST + kt*8;
                unsigned bh0 = __float_as_uint(Ksh[br + t    ]);
                unsigned bh1 = __float_as_uint(Ksh[br + t + 4]);
                unsigned bl0 = __float_as_uint(Ksl[br + t    ]);
                unsigned bl1 = __float_as_uint(Ksl[br + t + 4]);
                mma8(s[nt], ql[kt], bh0, bh1);
                mma8(s[nt], qh[kt], bl0, bl1);
                mma8(s[nt], qh[kt], bh0, bh1);
            }
        }

        // distance bias + mask on C-fragments
        #pragma unroll
        for (int nt = 0; nt < 8; nt++) {
            int col = k0 + nt*8 + 2*t;
            float2 d0 = *(const float2*)(db + (size_t)qr0 * LL + col);
            float2 d1 = *(const float2*)(db + (size_t)(qr0 + 8) * LL + col);
            unsigned short mk0 = *(const unsigned short*)(mb + (size_t)qr0 * LL + col);
            unsigned short mk1 = *(const unsigned short*)(mb + (size_t)(qr0 + 8) * LL + col);
            s[nt][0] -= d0.x * wb; if (mk0 & 0xffu) s[nt][0] = -1e9f;
            s[nt][1] -= d0.y * wb; if (mk0 >> 8)    s[nt][1] = -1e9f;
            s[nt][2] -= d1.x * wb; if (mk1 & 0xffu) s[nt][2] = -1e9f;
            s[nt][3] -= d1.y * wb; if (mk1 >> 8)    s[nt][3] = -1e9f;
        }

        // online softmax; row i=0 -> s[*][0..1], row i=1 (g+8) -> s[*][2..3]
        #pragma unroll
        for (int i = 0; i < 2; i++) {
            float mx = -1e30f;
            #pragma unroll
            for (int nt = 0; nt < 8; nt++)
                mx = fmaxf(mx, fmaxf(s[nt][2*i], s[nt][2*i + 1]));
            mx = fmaxf(mx, __shfl_xor_sync(0xffffffffu, mx, 1));
            mx = fmaxf(mx, __shfl_xor_sync(0xffffffffu, mx, 2));
            float mnew  = fmaxf(mrow[i], mx);
            float alpha = __expf(mrow[i] - mnew);
            float sum = 0.f;
            #pragma unroll
            for (int nt = 0; nt < 8; nt++) {
                s[nt][2*i]     = __expf(s[nt][2*i]     - mnew);
                s[nt][2*i + 1] = __expf(s[nt][2*i + 1] - mnew);
                sum += s[nt][2*i] + s[nt][2*i + 1];
            }
            sum += __shfl_xor_sync(0xffffffffu, sum, 1);
            sum += __shfl_xor_sync(0xffffffffu, sum, 2);
            lrow[i] = lrow[i] * alpha + sum;
            mrow[i] = mnew;
            #pragma unroll
            for (int nt = 0; nt < 8; nt++) {
                o[nt][2*i]     *= alpha;
                o[nt][2*i + 1] *= alpha;
            }
        }

        // P (tf32-rna rounded) -> smem. Per-warp private rows: syncwarp only.
        #pragma unroll
        for (int nt = 0; nt < 8; nt++) {
            *(float2*)&Ps[ pr0      * AST + nt*8 + 2*t] =
                make_float2(__uint_as_float(f2tf(s[nt][0])), __uint_as_float(f2tf(s[nt][1])));
            *(float2*)&Ps[(pr0 + 8) * AST + nt*8 + 2*t] =
                make_float2(__uint_as_float(f2tf(s[nt][2])), __uint_as_float(f2tf(s[nt][3])));
        }
        __syncwarp();

        // O += P @ V with 2xTF32 (P exact-rounded, V split hi/lo)
        #pragma unroll
        for (int kt = 0; kt < 8; kt++) {
            unsigned pa[4];
            pa[0] = __float_as_uint(Ps[ pr0      * AST + kt*8 + t    ]);
            pa[1] = __float_as_uint(Ps[(pr0 + 8) * AST + kt*8 + t    ]);
            pa[2] = __float_as_uint(Ps[ pr0      * AST + kt*8 + t + 4]);
            pa[3] = __float_as_uint(Ps[(pr0 + 8) * AST + kt*8 + t + 4]);
            #pragma unroll
            for (int nt = 0; nt < 8; nt++) {
                unsigned vh0 = __float_as_uint(Vsh[(kt*8 + t    ) * AST + nt*8 + g]);
                unsigned vh1 = __float_as_uint(Vsh[(kt*8 + t + 4) * AST + nt*8 + g]);
                unsigned vl0 = __float_as_uint(Vsl[(kt*8 + t    ) * AST + nt*8 + g]);
                unsigned vl1 = __float_as_uint(Vsl[(kt*8 + t + 4) * AST + nt*8 + g]);
                mma8(o[nt], pa, vl0, vl1);
                mma8(o[nt], pa, vh0, vh1);
            }
        }
    }

    // normalize + write X (B,L,D)
    float inv0 = 1.0f / lrow[0], inv1 = 1.0f / lrow[1];
    float* X0 = g_X + ((size_t)b * LL + qr0)     * DD + h * DKK;
    float* X1 = g_X + ((size_t)b * LL + qr0 + 8) * DD + h * DKK;
    #pragma unroll
    for (int nt = 0; nt < 8; nt++) {
        *(float2*)&X0[nt*8 + 2*t] = make_float2(o[nt][0] * inv0, o[nt][1] * inv0);
        *(float2*)&X1[nt*8 + 2*t] = make_float2(o[nt][2] * inv1, o[nt][3] * inv1);
    }
}

// ---------------------------------------------------------------------------
extern "C" void kernel_launch(void* const* d_in, const int* in_sizes, int n_in,
                              void* d_out, int out_size)
{
    const float* query = (const float*)d_in[0];
    const float* key   = (const float*)d_in[1];
    const float* value = (const float*)d_in[2];
    const float* dist  = (const float*)d_in[3];
    const unsigned char* mask = (const unsigned char*)d_in[4];
    const float* Wq = (const float*)d_in[5];
    const float* bq = (const float*)d_in[6];
    const float* Wk = (const float*)d_in[7];
    const float* bk = (const float*)d_in[8];
    const float* Wv = (const float*)d_in[9];
    const float* bv = (const float*)d_in[10];
    const float* Wo = (const float*)d_in[11];
    const float* bo = (const float*)d_in[12];
    const float* logwb = (const float*)d_in[13];

    void *pQ, *pK, *pV, *pX;
    cudaGetSymbolAddress(&pQ, g_Q);
    cudaGetSymbolAddress(&pK, g_K);
    cudaGetSymbolAddress(&pV, g_V);
    cudaGetSymbolAddress(&pX, g_X);

    cudaFuncSetAttribute(attn_tf32,
                         cudaFuncAttributeMaxDynamicSharedMemorySize, SMEM_ATTN);

    dim3 gg(DD / 64, (BB * LL) / 128);   // (8, 64)
    gemm_tf32<<<gg, 256>>>(query, Wq, bq, (float*)pQ, 1);
    gemm_tf32<<<gg, 256>>>(key,   Wk, bk, (float*)pK, 1);
    gemm_tf32<<<gg, 256>>>(value, Wv, bv, (float*)pV, 1);

    attn_tf32<<<dim3(LL / 64, BB * HH), 128, SMEM_ATTN>>>(dist, mask, logwb);

    gemm_tf32<<<gg, 256>>>((const float*)pX, Wo, bo, (float*)d_out, 0);
}